// round 1
// baseline (speedup 1.0000x reference)
#include <cuda_runtime.h>
#include <mma.h>
#include <math.h>
#include <stdint.h>

using namespace nvcuda;

// ---------------------------------------------------------------------------
// Problem constants (fixed by setup_inputs)
// ---------------------------------------------------------------------------
constexpr int D = 256;           // d_model
constexpr int NSTR = 6;
constexpr int NSCA = 20;
constexpr int TK = 4;            // top-k
constexpr int BATCH = 32768;
constexpr int T_TOK = BATCH * TK;  // 131072 tokens
constexpr float LN_EPS = 1e-5f;

constexpr int BKK = 16;          // K tile
constexpr int NTHREADS = 256;    // 8 warps

// ---------------------------------------------------------------------------
// Device scratch (static: no allocations allowed)
// ---------------------------------------------------------------------------
__device__ float g_w[TK];
__device__ int   g_ti[TK];
__device__ int   g_tj[TK];

__device__ float g_h1  [(size_t)T_TOK * D];
__device__ float g_cross[(size_t)T_TOK * D];
__device__ float g_h2  [(size_t)T_TOK * D];
__device__ float g_dif [(size_t)T_TOK * D];
__device__ float g_h3  [(size_t)T_TOK * 2 * D];

// ---------------------------------------------------------------------------
// K0: top-k over 6x20 scores, softmax weights, index decode
// (matches jax.lax.top_k: descending order, ties -> smallest index)
// ---------------------------------------------------------------------------
__global__ void prep_kernel(const float* __restrict__ scores,
                            const float* __restrict__ tempp) {
  if (threadIdx.x != 0) return;
  const int NTOT = NSTR * NSCA;  // 120
  bool used[NSTR * NSCA] = {};
  float vals[TK]; int idx[TK];
  for (int r = 0; r < TK; r++) {
    float best = -INFINITY; int bi = 0;
    for (int i = 0; i < NTOT; i++) {
      if (!used[i]) {
        float v = scores[i];
        if (v > best) { best = v; bi = i; }
      }
    }
    used[bi] = true; vals[r] = best; idx[r] = bi;
  }
  float tmp = fmaxf(tempp[0], 0.1f);
  float m = vals[0];  // descending -> max first
  float e[TK]; float se = 0.f;
  for (int r = 0; r < TK; r++) { e[r] = expf((vals[r] - m) / tmp); se += e[r]; }
  for (int r = 0; r < TK; r++) {
    g_w[r]  = e[r] / se;
    g_ti[r] = idx[r] / NSCA;
    g_tj[r] = idx[r] % NSCA;
  }
}

// ---------------------------------------------------------------------------
// Generic fused-A-loader TF32 WMMA GEMM.
// STAGE 1: A = [s | c | s*c]        (gather)     -> relu(A@cm_w1+b1) -> g_h1
// STAGE 2: A = g_h1                              ->      A@cm_w2+b2  -> g_cross
// STAGE 3: A = [s-c | |s-c|]        (gather)     -> relu(A@df_w1+b1) -> g_h2
// STAGE 4: A = g_h2                              ->      A@df_w2+b2  -> g_dif
// STAGE 5: A = [cross | dif | s*c]  (mixed)      -> relu(A@fu_w1+b1) -> g_h3
// STAGE 6: A = g_h3 (ld 512)  -> A@fu_w2+b2 -> LN -> weighted k-sum -> out
// ---------------------------------------------------------------------------
struct GArgs {
  const float* a0; const float* a1; const float* a2; const float* a3;
  const float* W;  const float* bias;
  float* out;
  const float* lng; const float* lnb;
};

template<int STAGE, int BM, int BN, int WMN, int WNN, int KTOT, int NTOT, bool RELU>
__global__ __launch_bounds__(NTHREADS)
void gemm_stage(GArgs g) {
  extern __shared__ float smem[];
  float* sA = smem;                 // [BM][BKK]
  float* sB = sA + BM * BKK;        // [BKK][BN]
  float* sC = sB + BKK * BN;        // [BM][BN]

  const int tid  = threadIdx.x;
  const int warp = tid >> 5;
  const int lane = tid & 31;
  const int wm = warp / WNN;
  const int wn = warp % WNN;
  constexpr int WM = BM / WMN;
  constexpr int WN = BN / WNN;
  constexpr int MI = WM / 16;
  constexpr int NI = WN / 16;
  constexpr int RPT = BM / 64;      // A-staging row-chunks per thread

  const int tBase = blockIdx.y * BM;
  const int nBase = blockIdx.x * BN;

  const int ar = tid >> 2;          // 0..63 (row within 64-row chunk)
  const int ac = (tid & 3) << 2;    // 0,4,8,12 (col, float4 granularity)

  const float* rowS[RPT];
  const float* rowC[RPT];
  if constexpr (STAGE == 1 || STAGE == 3 || STAGE == 5) {
    const float* sbase; const float* cbase;
    if constexpr (STAGE == 5) { sbase = g.a2; cbase = g.a3; }
    else                      { sbase = g.a0; cbase = g.a1; }
    #pragma unroll
    for (int rr = 0; rr < RPT; rr++) {
      int t = tBase + ar + rr * 64;
      int b = t >> 2, kk = t & 3;
      rowS[rr] = sbase + ((size_t)b * NSTR + g_ti[kk]) * D;
      rowC[rr] = cbase + ((size_t)b * NSCA + g_tj[kk]) * D;
    }
  }

  wmma::fragment<wmma::accumulator, 16, 16, 8, float> acc[MI][NI];
  #pragma unroll
  for (int mi = 0; mi < MI; mi++)
    #pragma unroll
    for (int ni = 0; ni < NI; ni++)
      wmma::fill_fragment(acc[mi][ni], 0.0f);

  for (int k0 = 0; k0 < KTOT; k0 += BKK) {
    // ---- stage A tile (fused gather / elementwise) ----
    #pragma unroll
    for (int rr = 0; rr < RPT; rr++) {
      const int r = ar + rr * 64;
      float4 v;
      if constexpr (STAGE == 1) {
        const int region = k0 >> 8;
        const int kk = (k0 & 255) + ac;
        if (region == 0)      v = *(const float4*)(rowS[rr] + kk);
        else if (region == 1) v = *(const float4*)(rowC[rr] + kk);
        else {
          float4 a = *(const float4*)(rowS[rr] + kk);
          float4 c = *(const float4*)(rowC[rr] + kk);
          v = make_float4(a.x*c.x, a.y*c.y, a.z*c.z, a.w*c.w);
        }
      } else if constexpr (STAGE == 3) {
        const int region = k0 >> 8;
        const int kk = (k0 & 255) + ac;
        float4 a = *(const float4*)(rowS[rr] + kk);
        float4 c = *(const float4*)(rowC[rr] + kk);
        float4 dv = make_float4(a.x-c.x, a.y-c.y, a.z-c.z, a.w-c.w);
        if (region == 1)
          dv = make_float4(fabsf(dv.x), fabsf(dv.y), fabsf(dv.z), fabsf(dv.w));
        v = dv;
      } else if constexpr (STAGE == 5) {
        const int region = k0 >> 8;
        const int kk = (k0 & 255) + ac;
        const int t = tBase + r;
        if (region == 0)      v = *(const float4*)(g.a0 + (size_t)t * D + kk);
        else if (region == 1) v = *(const float4*)(g.a1 + (size_t)t * D + kk);
        else {
          float4 a = *(const float4*)(rowS[rr] + kk);
          float4 c = *(const float4*)(rowC[rr] + kk);
          v = make_float4(a.x*c.x, a.y*c.y, a.z*c.z, a.w*c.w);
        }
      } else {
        constexpr int LDA = (STAGE == 6) ? 2 * D : D;
        const int t = tBase + r;
        v = *(const float4*)(g.a0 + (size_t)t * LDA + k0 + ac);
      }
      *(float4*)(sA + r * BKK + ac) = v;
    }
    // ---- stage B (weight) tile: W is row-major [KTOT][NTOT] ----
    {
      constexpr int NF4 = BKK * BN / 4;
      for (int i = tid; i < NF4; i += NTHREADS) {
        const int kr = i / (BN / 4);
        const int nc = (i - kr * (BN / 4)) << 2;
        *(float4*)(sB + kr * BN + nc) =
            *(const float4*)(g.W + (size_t)(k0 + kr) * NTOT + nBase + nc);
      }
    }
    __syncthreads();

    #pragma unroll
    for (int ks = 0; ks < BKK; ks += 8) {
      wmma::fragment<wmma::matrix_a, 16, 16, 8, wmma::precision::tf32, wmma::row_major> af[MI];
      wmma::fragment<wmma::matrix_b, 16, 16, 8, wmma::precision::tf32, wmma::row_major> bf[NI];
      #pragma unroll
      for (int mi = 0; mi < MI; mi++) {
        wmma::load_matrix_sync(af[mi], sA + (wm * WM + mi * 16) * BKK + ks, BKK);
        #pragma unroll
        for (int e = 0; e < af[mi].num_elements; e++)
          af[mi].x[e] = wmma::__float_to_tf32(af[mi].x[e]);
      }
      #pragma unroll
      for (int ni = 0; ni < NI; ni++) {
        wmma::load_matrix_sync(bf[ni], sB + ks * BN + wn * WN + ni * 16, BN);
        #pragma unroll
        for (int e = 0; e < bf[ni].num_elements; e++)
          bf[ni].x[e] = wmma::__float_to_tf32(bf[ni].x[e]);
      }
      #pragma unroll
      for (int mi = 0; mi < MI; mi++)
        #pragma unroll
        for (int ni = 0; ni < NI; ni++)
          wmma::mma_sync(acc[mi][ni], af[mi], bf[ni], acc[mi][ni]);
    }
    __syncthreads();
  }

  // ---- accumulators -> sC ----
  #pragma unroll
  for (int mi = 0; mi < MI; mi++)
    #pragma unroll
    for (int ni = 0; ni < NI; ni++)
      wmma::store_matrix_sync(sC + (wm * WM + mi * 16) * BN + wn * WN + ni * 16,
                              acc[mi][ni], BN, wmma::mem_row_major);
  __syncthreads();

  if constexpr (STAGE != 6) {
    // bias (+relu) epilogue -> global intermediate
    for (int i = tid; i < BM * BN; i += NTHREADS) {
      const int r = i / BN;
      const int n = i - r * BN;
      float v = sC[i] + g.bias[nBase + n];
      if (RELU) v = fmaxf(v, 0.0f);
      g.out[(size_t)(tBase + r) * NTOT + nBase + n] = v;
    }
  } else {
    // bias -> layernorm -> weighted top-k sum -> final output
    for (int i = tid; i < BM * BN; i += NTHREADS) {
      const int n = i & (BN - 1);
      sC[i] += g.bias[n];
    }
    __syncthreads();
    constexpr int RPW = BM / (NTHREADS / 32);   // rows per warp
    #pragma unroll
    for (int rr = 0; rr < RPW; rr++) {
      const int row = warp * RPW + rr;
      float s1 = 0.f, s2 = 0.f;
      #pragma unroll
      for (int c = 0; c < BN / 32; c++) {
        float x = sC[row * BN + c * 32 + lane];
        s1 += x; s2 += x * x;
      }
      #pragma unroll
      for (int o = 16; o > 0; o >>= 1) {
        s1 += __shfl_xor_sync(0xffffffffu, s1, o);
        s2 += __shfl_xor_sync(0xffffffffu, s2, o);
      }
      const float mu  = s1 / BN;
      const float var = s2 / BN - mu * mu;
      const float inv = rsqrtf(var + LN_EPS);
      #pragma unroll
      for (int c = 0; c < BN / 32; c++) {
        const int col = c * 32 + lane;
        float x = sC[row * BN + col];
        sC[row * BN + col] = (x - mu) * inv * g.lng[col] + g.lnb[col];
      }
    }
    __syncthreads();
    const float w0 = g_w[0], w1 = g_w[1], w2 = g_w[2], w3 = g_w[3];
    for (int i = tid; i < (BM / 4) * BN; i += NTHREADS) {
      const int bi = i / BN;
      const int n  = i - bi * BN;
      const float* base = sC + (size_t)(bi * 4) * BN + n;
      float v = w0 * base[0] + w1 * base[BN] + w2 * base[2 * BN] + w3 * base[3 * BN];
      g.out[(size_t)((tBase >> 2) + bi) * BN + n] = v;
    }
  }
}

// ---------------------------------------------------------------------------
// Host launcher (graph-capturable: kernel launches only)
// ---------------------------------------------------------------------------
static inline size_t smem_size(int BM, int BN) {
  return (size_t)(BM * BKK + BKK * BN + BM * BN) * sizeof(float);
}

extern "C" void kernel_launch(void* const* d_in, const int* in_sizes, int n_in,
                              void* d_out, int out_size) {
  const float* str   = (const float*)d_in[0];
  const float* sca   = (const float*)d_in[1];
  const float* pair  = (const float*)d_in[2];
  const float* temp  = (const float*)d_in[3];
  const float* cm_w1 = (const float*)d_in[4];
  const float* cm_b1 = (const float*)d_in[5];
  const float* cm_w2 = (const float*)d_in[6];
  const float* cm_b2 = (const float*)d_in[7];
  const float* df_w1 = (const float*)d_in[8];
  const float* df_b1 = (const float*)d_in[9];
  const float* df_w2 = (const float*)d_in[10];
  const float* df_b2 = (const float*)d_in[11];
  const float* fu_w1 = (const float*)d_in[12];
  const float* fu_b1 = (const float*)d_in[13];
  const float* fu_w2 = (const float*)d_in[14];
  const float* fu_b2 = (const float*)d_in[15];
  const float* lng   = (const float*)d_in[16];
  const float* lnb   = (const float*)d_in[17];
  float* out = (float*)d_out;

  float *h1, *cross, *h2, *dif, *h3;
  cudaGetSymbolAddress((void**)&h1,    g_h1);
  cudaGetSymbolAddress((void**)&cross, g_cross);
  cudaGetSymbolAddress((void**)&h2,    g_h2);
  cudaGetSymbolAddress((void**)&dif,   g_dif);
  cudaGetSymbolAddress((void**)&h3,    g_h3);

  prep_kernel<<<1, 32>>>(pair, temp);

  const size_t sm15 = smem_size(128, 128);
  const size_t sm6  = smem_size(64, 256);

  { // stage 1: h1 = relu([s|c|s*c] @ cm_w1 + b1)
    auto k = gemm_stage<1, 128, 128, 4, 2, 768, 256, true>;
    cudaFuncSetAttribute(k, cudaFuncAttributeMaxDynamicSharedMemorySize, (int)sm15);
    GArgs a{str, sca, nullptr, nullptr, cm_w1, cm_b1, h1, nullptr, nullptr};
    k<<<dim3(2, T_TOK / 128), NTHREADS, sm15>>>(a);
  }
  { // stage 2: cross = h1 @ cm_w2 + b2
    auto k = gemm_stage<2, 128, 128, 4, 2, 256, 256, false>;
    cudaFuncSetAttribute(k, cudaFuncAttributeMaxDynamicSharedMemorySize, (int)sm15);
    GArgs a{h1, nullptr, nullptr, nullptr, cm_w2, cm_b2, cross, nullptr, nullptr};
    k<<<dim3(2, T_TOK / 128), NTHREADS, sm15>>>(a);
  }
  { // stage 3: h2 = relu([s-c | |s-c|] @ df_w1 + b1)
    auto k = gemm_stage<3, 128, 128, 4, 2, 512, 256, true>;
    cudaFuncSetAttribute(k, cudaFuncAttributeMaxDynamicSharedMemorySize, (int)sm15);
    GArgs a{str, sca, nullptr, nullptr, df_w1, df_b1, h2, nullptr, nullptr};
    k<<<dim3(2, T_TOK / 128), NTHREADS, sm15>>>(a);
  }
  { // stage 4: dif = h2 @ df_w2 + b2
    auto k = gemm_stage<4, 128, 128, 4, 2, 256, 256, false>;
    cudaFuncSetAttribute(k, cudaFuncAttributeMaxDynamicSharedMemorySize, (int)sm15);
    GArgs a{h2, nullptr, nullptr, nullptr, df_w2, df_b2, dif, nullptr, nullptr};
    k<<<dim3(2, T_TOK / 128), NTHREADS, sm15>>>(a);
  }
  { // stage 5: h3 = relu([cross | dif | s*c] @ fu_w1 + b1), N = 512
    auto k = gemm_stage<5, 128, 128, 4, 2, 768, 512, true>;
    cudaFuncSetAttribute(k, cudaFuncAttributeMaxDynamicSharedMemorySize, (int)sm15);
    GArgs a{cross, dif, str, sca, fu_w1, fu_b1, h3, nullptr, nullptr};
    k<<<dim3(4, T_TOK / 128), NTHREADS, sm15>>>(a);
  }
  { // stage 6: fused = h3 @ fu_w2 + b2 -> LN -> weighted k-sum -> out
    auto k = gemm_stage<6, 64, 256, 2, 4, 512, 256, false>;
    cudaFuncSetAttribute(k, cudaFuncAttributeMaxDynamicSharedMemorySize, (int)sm6);
    GArgs a{h3, nullptr, nullptr, nullptr, fu_w2, fu_b2, out, lng, lnb};
    k<<<dim3(1, T_TOK / 64), NTHREADS, sm6>>>(a);
  }
}

// round 2
// speedup vs baseline: 1.4124x; 1.4124x over previous
#include <cuda_runtime.h>
#include <mma.h>
#include <math.h>
#include <stdint.h>

using namespace nvcuda;

constexpr int D = 256;
constexpr int NSTR = 6;
constexpr int NSCA = 20;
constexpr int TK = 4;
constexpr int BATCH = 32768;
constexpr int T_TOK = BATCH * TK;   // 131072
constexpr float LN_EPS = 1e-5f;

constexpr int BKK = 32;
constexpr int NTHREADS = 256;

// ---------------- device scratch (static) ----------------
__device__ float g_w[TK];
__device__ int   g_ti[TK];
__device__ int   g_tj[TK];

__device__ float g_h1  [(size_t)T_TOK * D];       // raw (pre-bias/relu)
__device__ float g_cross[(size_t)T_TOK * D];      // raw (pre-bias)
__device__ float g_h2  [(size_t)T_TOK * D];       // raw
__device__ float g_dif [(size_t)T_TOK * D];       // raw
__device__ float g_h3  [(size_t)T_TOK * 2 * D];   // raw

// ---------------- top-k / softmax prep ----------------
__global__ void prep_kernel(const float* __restrict__ scores,
                            const float* __restrict__ tempp) {
  if (threadIdx.x != 0) return;
  const int NTOT = NSTR * NSCA;
  bool used[NSTR * NSCA] = {};
  float vals[TK]; int idx[TK];
  for (int r = 0; r < TK; r++) {
    float best = -INFINITY; int bi = 0;
    for (int i = 0; i < NTOT; i++)
      if (!used[i]) { float v = scores[i]; if (v > best) { best = v; bi = i; } }
    used[bi] = true; vals[r] = best; idx[r] = bi;
  }
  float tmp = fmaxf(tempp[0], 0.1f);
  float m = vals[0], e[TK], se = 0.f;
  for (int r = 0; r < TK; r++) { e[r] = expf((vals[r] - m) / tmp); se += e[r]; }
  for (int r = 0; r < TK; r++) {
    g_w[r]  = e[r] / se;
    g_ti[r] = idx[r] / NSCA;
    g_tj[r] = idx[r] % NSCA;
  }
}

// ---------------- cp.async helpers ----------------
__device__ __forceinline__ void cp16(float* dst, const float* src) {
  uint32_t d = (uint32_t)__cvta_generic_to_shared(dst);
  asm volatile("cp.async.cg.shared.global [%0], [%1], 16;\n" :: "r"(d), "l"(src));
}
__device__ __forceinline__ void cp_commit() {
  asm volatile("cp.async.commit_group;\n");
}
template<int N> __device__ __forceinline__ void cp_wait() {
  asm volatile("cp.async.wait_group %0;\n" :: "n"(N));
}

struct GArgs {
  const float* a0; const float* a1; const float* a2; const float* a3;
  const float* ab0; const float* ab1;     // biases applied at A-load time
  const float* W;  const float* bias;     // output bias (stage 6 only)
  float* out;
  const float* lng; const float* lnb;
};

// ---------------------------------------------------------------------------
// Fused-A TF32 WMMA GEMM, double-buffered.
// S1: A=[s|c|s*c]                     -> raw @ cm_w1 -> g_h1
// S2: A=relu(h1+cm_b1)               -> raw @ cm_w2 -> g_cross
// S3: A=[s-c | |s-c|]                -> raw @ df_w1 -> g_h2
// S4: A=relu(h2+df_b1)               -> raw @ df_w2 -> g_dif
// S5: A=[cross+cm_b2 | dif+df_b2 | s*c] -> raw @ fu_w1 -> g_h3
// S6: A=relu(h3+fu_b1) -> @fu_w2 +fu_b2 -> LN -> weighted k-sum -> out
// ---------------------------------------------------------------------------
template<int STAGE, int BM, int BN, int WMN, int WNN, int KTOT, int NTOT>
__global__ __launch_bounds__(NTHREADS, 2)
void gemm_stage(GArgs g) {
  constexpr int SA_LD = BKK + 4;     // 36
  constexpr int SB_LD = BN + 4;
  constexpr int SC_LD = BN + 4;
  constexpr int RPT   = BM / 32;                      // float4s per thread (A)
  constexpr int NB4   = (BKK * (BN / 4)) / NTHREADS;  // float4s per thread (B)

  extern __shared__ float smem[];
  float* sAb[2] = { smem, smem + BM * SA_LD };
  float* sBb[2] = { smem + 2 * BM * SA_LD, smem + 2 * BM * SA_LD + BKK * SB_LD };

  const int tid = threadIdx.x, warp = tid >> 5, lane = tid & 31;
  const int wm = warp / WNN, wn = warp % WNN;
  constexpr int WM = BM / WMN, WN = BN / WNN;
  constexpr int MI = WM / 16, NI = WN / 16;
  const int tBase = blockIdx.y * BM;
  const int nBase = blockIdx.x * BN;
  const int ar = tid >> 3;            // 0..31
  const int ac = (tid & 7) << 2;      // 0..28

  const float* rowS[RPT];
  const float* rowC[RPT];
  if constexpr (STAGE == 1 || STAGE == 3 || STAGE == 5) {
    const float* sb = (STAGE == 5) ? g.a2 : g.a0;
    const float* cb = (STAGE == 5) ? g.a3 : g.a1;
    #pragma unroll
    for (int rr = 0; rr < RPT; rr++) {
      int t = tBase + ar + rr * 32;
      int b = t >> 2, k = t & 3;
      rowS[rr] = sb + ((size_t)b * NSTR + g_ti[k]) * D;
      rowC[rr] = cb + ((size_t)b * NSCA + g_tj[k]) * D;
    }
  }

  auto loadA = [&](int k0, float4* va) {
    #pragma unroll
    for (int rr = 0; rr < RPT; rr++) {
      const int t = tBase + ar + rr * 32;
      if constexpr (STAGE == 1) {
        const int region = k0 >> 8, kk = (k0 & 255) + ac;
        if (region == 0)      va[rr] = *(const float4*)(rowS[rr] + kk);
        else if (region == 1) va[rr] = *(const float4*)(rowC[rr] + kk);
        else {
          float4 a = *(const float4*)(rowS[rr] + kk);
          float4 c = *(const float4*)(rowC[rr] + kk);
          va[rr] = make_float4(a.x*c.x, a.y*c.y, a.z*c.z, a.w*c.w);
        }
      } else if constexpr (STAGE == 3) {
        const int region = k0 >> 8, kk = (k0 & 255) + ac;
        float4 a = *(const float4*)(rowS[rr] + kk);
        float4 c = *(const float4*)(rowC[rr] + kk);
        float4 dv = make_float4(a.x-c.x, a.y-c.y, a.z-c.z, a.w-c.w);
        if (region == 1)
          dv = make_float4(fabsf(dv.x), fabsf(dv.y), fabsf(dv.z), fabsf(dv.w));
        va[rr] = dv;
      } else if constexpr (STAGE == 5) {
        const int region = k0 >> 8, kk = (k0 & 255) + ac;
        if (region == 2) {
          float4 a = *(const float4*)(rowS[rr] + kk);
          float4 c = *(const float4*)(rowC[rr] + kk);
          va[rr] = make_float4(a.x*c.x, a.y*c.y, a.z*c.z, a.w*c.w);
        } else {
          const float* src  = region ? g.a1  : g.a0;
          const float* bsrc = region ? g.ab1 : g.ab0;
          float4 a = *(const float4*)(src + (size_t)t * D + kk);
          float4 b = *(const float4*)(bsrc + kk);
          va[rr] = make_float4(a.x+b.x, a.y+b.y, a.z+b.z, a.w+b.w);
        }
      } else {  // stages 2, 4, 6 : relu(raw + bias), lda == KTOT
        const int kk = k0 + ac;
        float4 a = *(const float4*)(g.a0 + (size_t)t * KTOT + kk);
        float4 b = *(const float4*)(g.ab0 + kk);
        va[rr] = make_float4(fmaxf(a.x+b.x, 0.f), fmaxf(a.y+b.y, 0.f),
                             fmaxf(a.z+b.z, 0.f), fmaxf(a.w+b.w, 0.f));
      }
    }
  };
  auto storeA = [&](int buf, const float4* va) {
    #pragma unroll
    for (int rr = 0; rr < RPT; rr++)
      *(float4*)(sAb[buf] + (ar + rr * 32) * SA_LD + ac) = va[rr];
  };
  auto issueB = [&](int k0, int buf) {
    #pragma unroll
    for (int i = 0; i < NB4; i++) {
      const int lin = tid + i * NTHREADS;
      const int kr = lin / (BN / 4);
      const int nc = (lin % (BN / 4)) * 4;
      cp16(sBb[buf] + kr * SB_LD + nc,
           g.W + (size_t)(k0 + kr) * NTOT + nBase + nc);
    }
    cp_commit();
  };

  wmma::fragment<wmma::accumulator, 16, 16, 8, float> acc[MI][NI];
  #pragma unroll
  for (int mi = 0; mi < MI; mi++)
    #pragma unroll
    for (int ni = 0; ni < NI; ni++)
      wmma::fill_fragment(acc[mi][ni], 0.0f);

  float4 aReg[RPT];
  loadA(0, aReg);
  storeA(0, aReg);
  issueB(0, 0);

  constexpr int NSTEP = KTOT / BKK;
  for (int s = 0; s < NSTEP; s++) {
    const int cur = s & 1;
    cp_wait<0>();
    __syncthreads();            // sA[cur] + sB[cur] ready; prev iter fully done
    if (s + 1 < NSTEP) {
      loadA((s + 1) * BKK, aReg);     // global->regs, overlapped with mma
      issueB((s + 1) * BKK, cur ^ 1); // async copy, overlapped with mma
    }
    #pragma unroll
    for (int ks = 0; ks < BKK; ks += 8) {
      wmma::fragment<wmma::matrix_a, 16, 16, 8, wmma::precision::tf32, wmma::row_major> af[MI];
      wmma::fragment<wmma::matrix_b, 16, 16, 8, wmma::precision::tf32, wmma::row_major> bf[NI];
      #pragma unroll
      for (int mi = 0; mi < MI; mi++) {
        wmma::load_matrix_sync(af[mi], sAb[cur] + (wm * WM + mi * 16) * SA_LD + ks, SA_LD);
        #pragma unroll
        for (int e = 0; e < af[mi].num_elements; e++)
          af[mi].x[e] = wmma::__float_to_tf32(af[mi].x[e]);
      }
      #pragma unroll
      for (int ni = 0; ni < NI; ni++) {
        wmma::load_matrix_sync(bf[ni], sBb[cur] + ks * SB_LD + wn * WN + ni * 16, SB_LD);
        #pragma unroll
        for (int e = 0; e < bf[ni].num_elements; e++)
          bf[ni].x[e] = wmma::__float_to_tf32(bf[ni].x[e]);
      }
      #pragma unroll
      for (int mi = 0; mi < MI; mi++)
        #pragma unroll
        for (int ni = 0; ni < NI; ni++)
          wmma::mma_sync(acc[mi][ni], af[mi], bf[ni], acc[mi][ni]);
    }
    if (s + 1 < NSTEP) storeA(cur ^ 1, aReg);
  }

  if constexpr (STAGE != 6) {
    // raw accumulator -> global (bias/relu deferred to consumer)
    #pragma unroll
    for (int mi = 0; mi < MI; mi++)
      #pragma unroll
      for (int ni = 0; ni < NI; ni++)
        wmma::store_matrix_sync(
            g.out + (size_t)(tBase + wm * WM + mi * 16) * NTOT + nBase + wn * WN + ni * 16,
            acc[mi][ni], NTOT, wmma::mem_row_major);
  } else {
    // epilogue: +fu_b2 -> LN -> weighted top-k sum.  sC aliases the loop smem.
    float* sC = smem;
    __syncthreads();
    #pragma unroll
    for (int mi = 0; mi < MI; mi++)
      #pragma unroll
      for (int ni = 0; ni < NI; ni++)
        wmma::store_matrix_sync(sC + (wm * WM + mi * 16) * SC_LD + wn * WN + ni * 16,
                                acc[mi][ni], SC_LD, wmma::mem_row_major);
    __syncthreads();
    constexpr int RPW = BM / (NTHREADS / 32);   // rows per warp
    #pragma unroll
    for (int rr = 0; rr < RPW; rr++) {
      const int row = warp * RPW + rr;
      float s1 = 0.f, s2 = 0.f;
      #pragma unroll
      for (int c = 0; c < BN / 32; c++) {
        const int col = c * 32 + lane;
        float x = sC[row * SC_LD + col] + g.bias[col];
        s1 += x; s2 += x * x;
      }
      #pragma unroll
      for (int o = 16; o > 0; o >>= 1) {
        s1 += __shfl_xor_sync(0xffffffffu, s1, o);
        s2 += __shfl_xor_sync(0xffffffffu, s2, o);
      }
      const float mu  = s1 / BN;
      const float var = s2 / BN - mu * mu;
      const float inv = rsqrtf(var + LN_EPS);
      #pragma unroll
      for (int c = 0; c < BN / 32; c++) {
        const int col = c * 32 + lane;
        float x = sC[row * SC_LD + col] + g.bias[col];
        sC[row * SC_LD + col] = (x - mu) * inv * g.lng[col] + g.lnb[col];
      }
    }
    __syncthreads();
    const float w0 = g_w[0], w1 = g_w[1], w2 = g_w[2], w3 = g_w[3];
    for (int i = tid; i < (BM / 4) * BN; i += NTHREADS) {
      const int bi = i >> 8;           // BN == 256
      const int n  = i & 255;
      const float* base = sC + (size_t)(bi * 4) * SC_LD + n;
      float v = w0 * base[0] + w1 * base[SC_LD] + w2 * base[2 * SC_LD] + w3 * base[3 * SC_LD];
      g.out[(size_t)((tBase >> 2) + bi) * 256 + n] = v;
    }
  }
}

// ---------------------------------------------------------------------------
static inline size_t loop_smem(int BM, int BN) {
  return (size_t)(2 * BM * (BKK + 4) + 2 * BKK * (BN + 4)) * sizeof(float);
}

extern "C" void kernel_launch(void* const* d_in, const int* in_sizes, int n_in,
                              void* d_out, int out_size) {
  const float* str   = (const float*)d_in[0];
  const float* sca   = (const float*)d_in[1];
  const float* pair  = (const float*)d_in[2];
  const float* temp  = (const float*)d_in[3];
  const float* cm_w1 = (const float*)d_in[4];
  const float* cm_b1 = (const float*)d_in[5];
  const float* cm_w2 = (const float*)d_in[6];
  const float* cm_b2 = (const float*)d_in[7];
  const float* df_w1 = (const float*)d_in[8];
  const float* df_b1 = (const float*)d_in[9];
  const float* df_w2 = (const float*)d_in[10];
  const float* df_b2 = (const float*)d_in[11];
  const float* fu_w1 = (const float*)d_in[12];
  const float* fu_b1 = (const float*)d_in[13];
  const float* fu_w2 = (const float*)d_in[14];
  const float* fu_b2 = (const float*)d_in[15];
  const float* lng   = (const float*)d_in[16];
  const float* lnb   = (const float*)d_in[17];
  float* out = (float*)d_out;

  float *h1, *cross, *h2, *dif, *h3;
  cudaGetSymbolAddress((void**)&h1,    g_h1);
  cudaGetSymbolAddress((void**)&cross, g_cross);
  cudaGetSymbolAddress((void**)&h2,    g_h2);
  cudaGetSymbolAddress((void**)&dif,   g_dif);
  cudaGetSymbolAddress((void**)&h3,    g_h3);

  prep_kernel<<<1, 32>>>(pair, temp);

  const size_t smA = loop_smem(128, 128);   // 70656 B
  const size_t smB = loop_smem(64, 256);    // 84992 B (sC aliased inside)

  { auto k = gemm_stage<1, 128, 128, 4, 2, 768, 256>;
    cudaFuncSetAttribute(k, cudaFuncAttributeMaxDynamicSharedMemorySize, (int)smA);
    GArgs a{str, sca, nullptr, nullptr, nullptr, nullptr, cm_w1, nullptr, h1, nullptr, nullptr};
    k<<<dim3(2, T_TOK / 128), NTHREADS, smA>>>(a); }
  { auto k = gemm_stage<2, 128, 128, 4, 2, 256, 256>;
    cudaFuncSetAttribute(k, cudaFuncAttributeMaxDynamicSharedMemorySize, (int)smA);
    GArgs a{h1, nullptr, nullptr, nullptr, cm_b1, nullptr, cm_w2, nullptr, cross, nullptr, nullptr};
    k<<<dim3(2, T_TOK / 128), NTHREADS, smA>>>(a); }
  { auto k = gemm_stage<3, 128, 128, 4, 2, 512, 256>;
    cudaFuncSetAttribute(k, cudaFuncAttributeMaxDynamicSharedMemorySize, (int)smA);
    GArgs a{str, sca, nullptr, nullptr, nullptr, nullptr, df_w1, nullptr, h2, nullptr, nullptr};
    k<<<dim3(2, T_TOK / 128), NTHREADS, smA>>>(a); }
  { auto k = gemm_stage<4, 128, 128, 4, 2, 256, 256>;
    cudaFuncSetAttribute(k, cudaFuncAttributeMaxDynamicSharedMemorySize, (int)smA);
    GArgs a{h2, nullptr, nullptr, nullptr, df_b1, nullptr, df_w2, nullptr, dif, nullptr, nullptr};
    k<<<dim3(2, T_TOK / 128), NTHREADS, smA>>>(a); }
  { auto k = gemm_stage<5, 128, 128, 4, 2, 768, 512>;
    cudaFuncSetAttribute(k, cudaFuncAttributeMaxDynamicSharedMemorySize, (int)smA);
    GArgs a{cross, dif, str, sca, cm_b2, df_b2, fu_w1, nullptr, h3, nullptr, nullptr};
    k<<<dim3(4, T_TOK / 128), NTHREADS, smA>>>(a); }
  { auto k = gemm_stage<6, 64, 256, 2, 4, 512, 256>;
    cudaFuncSetAttribute(k, cudaFuncAttributeMaxDynamicSharedMemorySize, (int)smB);
    GArgs a{h3, nullptr, nullptr, nullptr, fu_b1, nullptr, fu_w2, fu_b2, out, lng, lnb};
    k<<<dim3(1, T_TOK / 64), NTHREADS, smB>>>(a); }
}

// round 6
// speedup vs baseline: 2.3621x; 1.6725x over previous
#include <cuda_runtime.h>
#include <cuda_fp16.h>
#include <mma.h>
#include <math.h>
#include <stdint.h>

using namespace nvcuda;

constexpr int D = 256;
constexpr int NSTR = 6;
constexpr int NSCA = 20;
constexpr int TK = 4;
constexpr int BATCH = 32768;
constexpr int T_TOK = BATCH * TK;   // 131072
constexpr float LN_EPS = 1e-5f;

constexpr int BKK = 64;
constexpr int NTHREADS = 256;

// ---------------- device scratch ----------------
__device__ float g_w[TK];
__device__ int   g_ti[TK];
__device__ int   g_tj[TK];

__device__ __align__(16) float g_h1   [(size_t)T_TOK * D];
__device__ __align__(16) float g_cross[(size_t)T_TOK * D];
__device__ __align__(16) float g_h2   [(size_t)T_TOK * D];
__device__ __align__(16) float g_dif  [(size_t)T_TOK * D];
__device__ __align__(16) float g_h3   [(size_t)T_TOK * 2 * D];

// fp16 weights, original [K][N] layout
__device__ __align__(16) __half g_hw1[768 * 256];
__device__ __align__(16) __half g_hw2[256 * 256];
__device__ __align__(16) __half g_hw3[512 * 256];
__device__ __align__(16) __half g_hw4[256 * 256];
__device__ __align__(16) __half g_hw5[768 * 512];
__device__ __align__(16) __half g_hw6[512 * 256];

// ---------------- prep: top-k + softmax ----------------
__global__ void prep_kernel(const float* __restrict__ scores,
                            const float* __restrict__ tempp) {
  if (threadIdx.x != 0) return;
  const int NTOT = NSTR * NSCA;
  bool used[NSTR * NSCA] = {};
  float vals[TK]; int idx[TK];
  for (int r = 0; r < TK; r++) {
    float best = -INFINITY; int bi = 0;
    for (int i = 0; i < NTOT; i++)
      if (!used[i]) { float v = scores[i]; if (v > best) { best = v; bi = i; } }
    used[bi] = true; vals[r] = best; idx[r] = bi;
  }
  float tmp = fmaxf(tempp[0], 0.1f);
  float m = vals[0], e[TK], se = 0.f;
  for (int r = 0; r < TK; r++) { e[r] = expf((vals[r] - m) / tmp); se += e[r]; }
  for (int r = 0; r < TK; r++) {
    g_w[r]  = e[r] / se;
    g_ti[r] = idx[r] / NSCA;
    g_tj[r] = idx[r] % NSCA;
  }
}

// ---------------- fp32 -> fp16 weight conversion ----------------
__global__ void to_half_kernel(const float* __restrict__ src,
                               __half* __restrict__ dst, int n4) {
  int i = blockIdx.x * blockDim.x + threadIdx.x;
  if (i < n4) {
    float4 v = *(const float4*)(src + i * 4);
    __half2 a = __floats2half2_rn(v.x, v.y);
    __half2 b = __floats2half2_rn(v.z, v.w);
    *(uint2*)(dst + i * 4) = make_uint2(*(uint32_t*)&a, *(uint32_t*)&b);
  }
}

// ---------------- cp.async helpers ----------------
__device__ __forceinline__ void cp16(void* dst, const void* src) {
  uint32_t d = (uint32_t)__cvta_generic_to_shared(dst);
  asm volatile("cp.async.cg.shared.global [%0], [%1], 16;\n" :: "r"(d), "l"(src));
}
__device__ __forceinline__ void cp_commit() {
  asm volatile("cp.async.commit_group;\n");
}
template<int N> __device__ __forceinline__ void cp_wait() {
  asm volatile("cp.async.wait_group %0;\n" :: "n"(N));
}

__device__ __forceinline__ uint4 pack8(float4 f0, float4 f1) {
  __half2 a = __floats2half2_rn(f0.x, f0.y);
  __half2 b = __floats2half2_rn(f0.z, f0.w);
  __half2 c = __floats2half2_rn(f1.x, f1.y);
  __half2 d = __floats2half2_rn(f1.z, f1.w);
  return make_uint4(*(uint32_t*)&a, *(uint32_t*)&b, *(uint32_t*)&c, *(uint32_t*)&d);
}

struct GArgs {
  const float* a0; const float* a1; const float* a2; const float* a3;
  const float* ab0; const float* ab1;
  const __half* W;       // [K][NTOTAL] fp16
  const float* bias;     // stage 6 output bias
  float* out;
  const float* lng; const float* lnb;
};

// ---------------------------------------------------------------------------
// Fused-A fp16 WMMA GEMM, double-buffered, fp32 accum.
// ---------------------------------------------------------------------------
template<int STAGE, int KTOT, int NTOTAL, int BM, int BN>
__global__ __launch_bounds__(NTHREADS, 2)
void gemm_stage(GArgs g) {
  constexpr int SA_LD = BKK + 8;     // 72 halves (144 B rows)
  constexpr int SB_LD = BN + 8;
  constexpr int SC_LD = BN + 4;      // fp32, stage 6 only
  constexpr int WNN = (BM == 128) ? 2 : 4;
  constexpr int WM = 32, WN = 64;
  constexpr int MI = 2, NI = 4;
  constexpr int TPR = NTHREADS / BM;          // threads per A-row (2 or 4)
  constexpr int CPT = (BKK / 8) / TPR;        // 8-half chunks per thread
  constexpr int BCH = (BKK * BN / 8) / NTHREADS;  // B chunks per thread

  extern __shared__ char smem[];
  __half* sAb[2] = { (__half*)smem, (__half*)smem + BM * SA_LD };
  __half* sBb[2] = { (__half*)smem + 2 * BM * SA_LD,
                     (__half*)smem + 2 * BM * SA_LD + BKK * SB_LD };

  const int tid = threadIdx.x, warp = tid >> 5, lane = tid & 31;
  const int wm = warp / WNN, wn = warp % WNN;
  const int tBase = blockIdx.y * BM;
  const int nBase = blockIdx.x * BN;

  const int arow = tid / TPR;
  const int cb0  = (tid % TPR) * CPT;        // first chunk index in row
  const int t_tok = tBase + arow;

  const float *rS = nullptr, *rC = nullptr;
  if constexpr (STAGE == 1 || STAGE == 3 || STAGE == 5) {
    const float* sbp = (STAGE == 5) ? g.a2 : g.a0;
    const float* cbp = (STAGE == 5) ? g.a3 : g.a1;
    const int b = t_tok >> 2, k = t_tok & 3;
    rS = sbp + ((size_t)b * NSTR + g_ti[k]) * D;
    rC = cbp + ((size_t)b * NSCA + g_tj[k]) * D;
  }

  auto loadA = [&](int k0, uint4* va) {
    const int region = k0 >> 8;
    #pragma unroll
    for (int ci = 0; ci < CPT; ci++) {
      const int col = (cb0 + ci) * 8;
      const int gcol = k0 + col;
      const int kk = (k0 & 255) + col;
      float4 f0, f1;
      if constexpr (STAGE == 1) {
        if (region == 0)      { f0 = *(const float4*)(rS + kk); f1 = *(const float4*)(rS + kk + 4); }
        else if (region == 1) { f0 = *(const float4*)(rC + kk); f1 = *(const float4*)(rC + kk + 4); }
        else {
          float4 a0 = *(const float4*)(rS + kk), a1 = *(const float4*)(rS + kk + 4);
          float4 c0 = *(const float4*)(rC + kk), c1 = *(const float4*)(rC + kk + 4);
          f0 = make_float4(a0.x*c0.x, a0.y*c0.y, a0.z*c0.z, a0.w*c0.w);
          f1 = make_float4(a1.x*c1.x, a1.y*c1.y, a1.z*c1.z, a1.w*c1.w);
        }
      } else if constexpr (STAGE == 3) {
        float4 a0 = *(const float4*)(rS + kk), a1 = *(const float4*)(rS + kk + 4);
        float4 c0 = *(const float4*)(rC + kk), c1 = *(const float4*)(rC + kk + 4);
        f0 = make_float4(a0.x-c0.x, a0.y-c0.y, a0.z-c0.z, a0.w-c0.w);
        f1 = make_float4(a1.x-c1.x, a1.y-c1.y, a1.z-c1.z, a1.w-c1.w);
        if (region == 1) {
          f0 = make_float4(fabsf(f0.x), fabsf(f0.y), fabsf(f0.z), fabsf(f0.w));
          f1 = make_float4(fabsf(f1.x), fabsf(f1.y), fabsf(f1.z), fabsf(f1.w));
        }
      } else if constexpr (STAGE == 5) {
        if (region == 2) {
          float4 a0 = *(const float4*)(rS + kk), a1 = *(const float4*)(rS + kk + 4);
          float4 c0 = *(const float4*)(rC + kk), c1 = *(const float4*)(rC + kk + 4);
          f0 = make_float4(a0.x*c0.x, a0.y*c0.y, a0.z*c0.z, a0.w*c0.w);
          f1 = make_float4(a1.x*c1.x, a1.y*c1.y, a1.z*c1.z, a1.w*c1.w);
        } else {
          const float* src = region ? g.a1 : g.a0;
          const float* bb  = region ? g.ab1 : g.ab0;
          float4 a0 = *(const float4*)(src + (size_t)t_tok * D + kk);
          float4 a1 = *(const float4*)(src + (size_t)t_tok * D + kk + 4);
          float4 b0 = *(const float4*)(bb + kk);
          float4 b1 = *(const float4*)(bb + kk + 4);
          f0 = make_float4(a0.x+b0.x, a0.y+b0.y, a0.z+b0.z, a0.w+b0.w);
          f1 = make_float4(a1.x+b1.x, a1.y+b1.y, a1.z+b1.z, a1.w+b1.w);
        }
      } else {  // 2, 4, 6 : relu(raw + bias)
        float4 a0 = *(const float4*)(g.a0 + (size_t)t_tok * KTOT + gcol);
        float4 a1 = *(const float4*)(g.a0 + (size_t)t_tok * KTOT + gcol + 4);
        float4 b0 = *(const float4*)(g.ab0 + gcol);
        float4 b1 = *(const float4*)(g.ab0 + gcol + 4);
        f0 = make_float4(fmaxf(a0.x+b0.x,0.f), fmaxf(a0.y+b0.y,0.f),
                         fmaxf(a0.z+b0.z,0.f), fmaxf(a0.w+b0.w,0.f));
        f1 = make_float4(fmaxf(a1.x+b1.x,0.f), fmaxf(a1.y+b1.y,0.f),
                         fmaxf(a1.z+b1.z,0.f), fmaxf(a1.w+b1.w,0.f));
      }
      va[ci] = pack8(f0, f1);
    }
  };
  auto storeA = [&](int buf, const uint4* va) {
    #pragma unroll
    for (int ci = 0; ci < CPT; ci++)
      *(uint4*)(sAb[buf] + arow * SA_LD + (cb0 + ci) * 8) = va[ci];
  };
  auto issueB = [&](int k0, int buf) {
    #pragma unroll
    for (int i = 0; i < BCH; i++) {
      const int lin = tid + i * NTHREADS;
      const int kr = lin / (BN / 8);
      const int nc = (lin % (BN / 8)) * 8;
      cp16(sBb[buf] + kr * SB_LD + nc,
           g.W + (size_t)(k0 + kr) * NTOTAL + nBase + nc);
    }
    cp_commit();
  };

  wmma::fragment<wmma::accumulator, 16, 16, 16, float> acc[MI][NI];
  #pragma unroll
  for (int mi = 0; mi < MI; mi++)
    #pragma unroll
    for (int ni = 0; ni < NI; ni++)
      wmma::fill_fragment(acc[mi][ni], 0.0f);

  uint4 aReg[CPT];
  loadA(0, aReg);
  storeA(0, aReg);
  issueB(0, 0);

  constexpr int NSTEP = KTOT / BKK;
  for (int s = 0; s < NSTEP; s++) {
    const int cur = s & 1;
    cp_wait<0>();
    __syncthreads();
    if (s + 1 < NSTEP) {
      loadA((s + 1) * BKK, aReg);
      issueB((s + 1) * BKK, cur ^ 1);
    }
    #pragma unroll
    for (int ks = 0; ks < BKK; ks += 16) {
      wmma::fragment<wmma::matrix_a, 16, 16, 16, __half, wmma::row_major> af[MI];
      wmma::fragment<wmma::matrix_b, 16, 16, 16, __half, wmma::row_major> bf[NI];
      #pragma unroll
      for (int mi = 0; mi < MI; mi++)
        wmma::load_matrix_sync(af[mi], sAb[cur] + (wm * WM + mi * 16) * SA_LD + ks, SA_LD);
      #pragma unroll
      for (int ni = 0; ni < NI; ni++)
        wmma::load_matrix_sync(bf[ni], sBb[cur] + ks * SB_LD + wn * WN + ni * 16, SB_LD);
      #pragma unroll
      for (int mi = 0; mi < MI; mi++)
        #pragma unroll
        for (int ni = 0; ni < NI; ni++)
          wmma::mma_sync(acc[mi][ni], af[mi], bf[ni], acc[mi][ni]);
    }
    if (s + 1 < NSTEP) storeA(cur ^ 1, aReg);
  }

  if constexpr (STAGE != 6) {
    #pragma unroll
    for (int mi = 0; mi < MI; mi++)
      #pragma unroll
      for (int ni = 0; ni < NI; ni++)
        wmma::store_matrix_sync(
            g.out + (size_t)(tBase + wm * WM + mi * 16) * NTOTAL + nBase + wn * WN + ni * 16,
            acc[mi][ni], NTOTAL, wmma::mem_row_major);
  } else {
    float* sC = (float*)smem;
    __syncthreads();
    #pragma unroll
    for (int mi = 0; mi < MI; mi++)
      #pragma unroll
      for (int ni = 0; ni < NI; ni++)
        wmma::store_matrix_sync(sC + (wm * WM + mi * 16) * SC_LD + wn * WN + ni * 16,
                                acc[mi][ni], SC_LD, wmma::mem_row_major);
    __syncthreads();
    constexpr int RPW = BM / (NTHREADS / 32);
    #pragma unroll
    for (int rr = 0; rr < RPW; rr++) {
      const int row = warp * RPW + rr;
      float s1 = 0.f, s2 = 0.f;
      #pragma unroll
      for (int c = 0; c < BN / 32; c++) {
        const int col = c * 32 + lane;
        float x = sC[row * SC_LD + col] + g.bias[col];
        s1 += x; s2 += x * x;
      }
      #pragma unroll
      for (int o = 16; o > 0; o >>= 1) {
        s1 += __shfl_xor_sync(0xffffffffu, s1, o);
        s2 += __shfl_xor_sync(0xffffffffu, s2, o);
      }
      const float mu  = s1 / BN;
      const float var = s2 / BN - mu * mu;
      const float inv = rsqrtf(var + LN_EPS);
      #pragma unroll
      for (int c = 0; c < BN / 32; c++) {
        const int col = c * 32 + lane;
        float x = sC[row * SC_LD + col] + g.bias[col];
        sC[row * SC_LD + col] = (x - mu) * inv * g.lng[col] + g.lnb[col];
      }
    }
    __syncthreads();
    const float w0 = g_w[0], w1 = g_w[1], w2 = g_w[2], w3 = g_w[3];
    for (int i = tid; i < (BM / 4) * BN; i += NTHREADS) {
      const int bi = i >> 8;           // BN == 256
      const int n  = i & 255;
      const float* base = sC + (size_t)(bi * 4) * SC_LD + n;
      float v = w0 * base[0] + w1 * base[SC_LD] + w2 * base[2 * SC_LD] + w3 * base[3 * SC_LD];
      g.out[(size_t)((tBase >> 2) + bi) * 256 + n] = v;
    }
  }
}

// ---------------------------------------------------------------------------
extern "C" void kernel_launch(void* const* d_in, const int* in_sizes, int n_in,
                              void* d_out, int out_size) {
  const float* str   = (const float*)d_in[0];
  const float* sca   = (const float*)d_in[1];
  const float* pair  = (const float*)d_in[2];
  const float* temp  = (const float*)d_in[3];
  const float* cm_w1 = (const float*)d_in[4];
  const float* cm_b1 = (const float*)d_in[5];
  const float* cm_w2 = (const float*)d_in[6];
  const float* cm_b2 = (const float*)d_in[7];
  const float* df_w1 = (const float*)d_in[8];
  const float* df_b1 = (const float*)d_in[9];
  const float* df_w2 = (const float*)d_in[10];
  const float* df_b2 = (const float*)d_in[11];
  const float* fu_w1 = (const float*)d_in[12];
  const float* fu_b1 = (const float*)d_in[13];
  const float* fu_w2 = (const float*)d_in[14];
  const float* fu_b2 = (const float*)d_in[15];
  const float* lng   = (const float*)d_in[16];
  const float* lnb   = (const float*)d_in[17];
  float* out = (float*)d_out;

  float *h1, *cross, *h2, *dif, *h3;
  __half *hw1, *hw2, *hw3, *hw4, *hw5, *hw6;
  cudaGetSymbolAddress((void**)&h1,    g_h1);
  cudaGetSymbolAddress((void**)&cross, g_cross);
  cudaGetSymbolAddress((void**)&h2,    g_h2);
  cudaGetSymbolAddress((void**)&dif,   g_dif);
  cudaGetSymbolAddress((void**)&h3,    g_h3);
  cudaGetSymbolAddress((void**)&hw1,   g_hw1);
  cudaGetSymbolAddress((void**)&hw2,   g_hw2);
  cudaGetSymbolAddress((void**)&hw3,   g_hw3);
  cudaGetSymbolAddress((void**)&hw4,   g_hw4);
  cudaGetSymbolAddress((void**)&hw5,   g_hw5);
  cudaGetSymbolAddress((void**)&hw6,   g_hw6);

  prep_kernel<<<1, 32>>>(pair, temp);
  auto cvt = [&](const float* s, __half* d, int n) {
    to_half_kernel<<<(n / 4 + 255) / 256, 256>>>(s, d, n / 4);
  };
  cvt(cm_w1, hw1, 768 * 256);
  cvt(cm_w2, hw2, 256 * 256);
  cvt(df_w1, hw3, 512 * 256);
  cvt(df_w2, hw4, 256 * 256);
  cvt(fu_w1, hw5, 768 * 512);
  cvt(fu_w2, hw6, 512 * 256);

  // smem sizes (bytes)
  const size_t smA = (2 * 128 * 72 + 2 * BKK * 136) * sizeof(__half);   // 71680
  const size_t smB = (2 * 64 * 72 + 2 * BKK * 264) * sizeof(__half);    // 86016
  const int GY = T_TOK / 128;   // 1024

  { auto k = gemm_stage<1, 768, 256, 128, 128>;
    cudaFuncSetAttribute(k, cudaFuncAttributeMaxDynamicSharedMemorySize, (int)smA);
    GArgs a{str, sca, nullptr, nullptr, nullptr, nullptr, hw1, nullptr, h1, nullptr, nullptr};
    k<<<dim3(2, GY), NTHREADS, smA>>>(a); }
  { auto k = gemm_stage<2, 256, 256, 128, 128>;
    cudaFuncSetAttribute(k, cudaFuncAttributeMaxDynamicSharedMemorySize, (int)smA);
    GArgs a{h1, nullptr, nullptr, nullptr, cm_b1, nullptr, hw2, nullptr, cross, nullptr, nullptr};
    k<<<dim3(2, GY), NTHREADS, smA>>>(a); }
  { auto k = gemm_stage<3, 512, 256, 128, 128>;
    cudaFuncSetAttribute(k, cudaFuncAttributeMaxDynamicSharedMemorySize, (int)smA);
    GArgs a{str, sca, nullptr, nullptr, nullptr, nullptr, hw3, nullptr, h2, nullptr, nullptr};
    k<<<dim3(2, GY), NTHREADS, smA>>>(a); }
  { auto k = gemm_stage<4, 256, 256, 128, 128>;
    cudaFuncSetAttribute(k, cudaFuncAttributeMaxDynamicSharedMemorySize, (int)smA);
    GArgs a{h2, nullptr, nullptr, nullptr, df_b1, nullptr, hw4, nullptr, dif, nullptr, nullptr};
    k<<<dim3(2, GY), NTHREADS, smA>>>(a); }
  { auto k = gemm_stage<5, 768, 512, 128, 128>;
    cudaFuncSetAttribute(k, cudaFuncAttributeMaxDynamicSharedMemorySize, (int)smA);
    GArgs a{cross, dif, str, sca, cm_b2, df_b2, hw5, nullptr, h3, nullptr, nullptr};
    k<<<dim3(4, GY), NTHREADS, smA>>>(a); }
  { auto k = gemm_stage<6, 512, 256, 64, 256>;
    cudaFuncSetAttribute(k, cudaFuncAttributeMaxDynamicSharedMemorySize, (int)smB);
    GArgs a{h3, nullptr, nullptr, nullptr, fu_b1, nullptr, hw6, fu_b2, out, lng, lnb};
    k<<<dim3(1, T_TOK / 64), NTHREADS, smB>>>(a); }
}

// round 7
// speedup vs baseline: 3.9331x; 1.6651x over previous
#include <cuda_runtime.h>
#include <cuda_fp16.h>
#include <mma.h>
#include <math.h>
#include <stdint.h>

using namespace nvcuda;

constexpr int D = 256;
constexpr int NSTR = 6;
constexpr int NSCA = 20;
constexpr int TK = 4;
constexpr int BATCH = 32768;
constexpr int T_TOK = BATCH * TK;   // 131072
constexpr float LN_EPS = 1e-5f;

// ---------------- device scratch ----------------
__device__ float g_w[TK];
__device__ int   g_ti[TK];
__device__ int   g_tj[TK];

__device__ __align__(16) __half g_crossh[(size_t)T_TOK * D];  // cross_f + cm_b2, fp16
__device__ __align__(16) __half g_difh  [(size_t)T_TOK * D];  // diff_f + df_b2, fp16

// fp16 weights, original [K][N] layout
__device__ __align__(16) __half g_hw1[768 * 256];
__device__ __align__(16) __half g_hw2[256 * 256];
__device__ __align__(16) __half g_hw3[512 * 256];
__device__ __align__(16) __half g_hw4[256 * 256];
__device__ __align__(16) __half g_hw5[768 * 512];
__device__ __align__(16) __half g_hw6[512 * 256];

// ---------------- prep: top-k + softmax ----------------
__global__ void prep_kernel(const float* __restrict__ scores,
                            const float* __restrict__ tempp) {
  if (threadIdx.x != 0) return;
  const int NTOT = NSTR * NSCA;
  bool used[NSTR * NSCA] = {};
  float vals[TK]; int idx[TK];
  for (int r = 0; r < TK; r++) {
    float best = -INFINITY; int bi = 0;
    for (int i = 0; i < NTOT; i++)
      if (!used[i]) { float v = scores[i]; if (v > best) { best = v; bi = i; } }
    used[bi] = true; vals[r] = best; idx[r] = bi;
  }
  float tmp = fmaxf(tempp[0], 0.1f);
  float m = vals[0], e[TK], se = 0.f;
  for (int r = 0; r < TK; r++) { e[r] = expf((vals[r] - m) / tmp); se += e[r]; }
  for (int r = 0; r < TK; r++) {
    g_w[r]  = e[r] / se;
    g_ti[r] = idx[r] / NSCA;
    g_tj[r] = idx[r] % NSCA;
  }
}

// ---------------- fp32 -> fp16 weight conversion ----------------
__global__ void to_half_kernel(const float* __restrict__ src,
                               __half* __restrict__ dst, int n4) {
  int i = blockIdx.x * blockDim.x + threadIdx.x;
  if (i < n4) {
    float4 v = *(const float4*)(src + i * 4);
    __half2 a = __floats2half2_rn(v.x, v.y);
    __half2 b = __floats2half2_rn(v.z, v.w);
    *(uint2*)(dst + i * 4) = make_uint2(*(uint32_t*)&a, *(uint32_t*)&b);
  }
}

// ---------------- helpers ----------------
__device__ __forceinline__ void cp16(void* dst, const void* src) {
  uint32_t d = (uint32_t)__cvta_generic_to_shared(dst);
  asm volatile("cp.async.cg.shared.global [%0], [%1], 16;\n" :: "r"(d), "l"(src));
}
__device__ __forceinline__ void cp_commit() {
  asm volatile("cp.async.commit_group;\n");
}
template<int N> __device__ __forceinline__ void cp_wait() {
  asm volatile("cp.async.wait_group %0;\n" :: "n"(N));
}
__device__ __forceinline__ uint4 pack8(float4 f0, float4 f1) {
  __half2 a = __floats2half2_rn(f0.x, f0.y);
  __half2 b = __floats2half2_rn(f0.z, f0.w);
  __half2 c = __floats2half2_rn(f1.x, f1.y);
  __half2 d = __floats2half2_rn(f1.z, f1.w);
  return make_uint4(*(uint32_t*)&a, *(uint32_t*)&b, *(uint32_t*)&c, *(uint32_t*)&d);
}

using FragAcc = wmma::fragment<wmma::accumulator, 16, 16, 16, float>;
using FragAccH = wmma::fragment<wmma::accumulator, 16, 16, 16, __half>;
using FragA = wmma::fragment<wmma::matrix_a, 16, 16, 16, __half, wmma::row_major>;
using FragB = wmma::fragment<wmma::matrix_b, 16, 16, 16, __half, wmma::row_major>;

// ===========================================================================
// Kernel A/B: fused (GEMM_a K=K1 with computed A) -> relu -> smem h1 ->
//             (GEMM_b K=256) -> +bias -> fp16 global out.
// PAIR 0: A = [s | c | s*c]   (cm branch)
// PAIR 1: A = [s-c | |s-c|]   (df branch)
// CTA: 512 threads, 128 tokens, full N=256.
// ===========================================================================
template<int PAIR, int K1>
__global__ __launch_bounds__(512, 1)
void fused12(const float* __restrict__ s_enc, const float* __restrict__ c_enc,
             const __half* __restrict__ W1, const float* __restrict__ b1,
             const __half* __restrict__ W2, const float* __restrict__ b2,
             __half* __restrict__ outp) {
  extern __shared__ char smem[];
  __half* h1 = (__half*)smem;                                  // 128x264
  __half* Bb[2] = { (__half*)(smem + 67584), (__half*)(smem + 101376) };  // 64x264 ea
  __half* Ab[2] = { (__half*)(smem + 135168), (__half*)(smem + 153600) }; // 128x72 ea
  float* bias32 = (float*)(smem + 172032);                     // 16x264 fp32

  const int tid = threadIdx.x, warp = tid >> 5;
  const int wm = warp >> 2, wn = warp & 3;       // 4x4 warps; warp tile 32x64
  const int tBase = blockIdx.x * 128;

  const int row = tid >> 2;                      // 0..127
  const int colg = (tid & 3) * 16;               // 0,16,32,48
  const int t_tok = tBase + row;
  const int bidx = t_tok >> 2, kidx = t_tok & 3;
  const float* rS = s_enc + ((size_t)bidx * NSTR + g_ti[kidx]) * D;
  const float* rC = c_enc + ((size_t)bidx * NSCA + g_tj[kidx]) * D;

  // bias tile = b1 replicated over 16 rows
  if (tid < 264) {
    float v = (tid < 256) ? b1[tid] : 0.f;
    #pragma unroll
    for (int r = 0; r < 16; r++) bias32[r * 264 + tid] = v;
  }
  __syncthreads();

  FragAcc acc[2][4];
  #pragma unroll
  for (int mi = 0; mi < 2; mi++)
    #pragma unroll
    for (int ni = 0; ni < 4; ni++)
      wmma::load_matrix_sync(acc[mi][ni], bias32 + wn * 64 + ni * 16, 264,
                             wmma::mem_row_major);

  auto stageA = [&](int s, int buf) {
    const int k0 = s * 64;
    const int region = k0 >> 8;
    #pragma unroll
    for (int c8 = 0; c8 < 16; c8 += 8) {
      const int kk = (k0 & 255) + colg + c8;
      float4 f0, f1;
      if constexpr (PAIR == 0) {
        if (region == 0)      { f0 = *(const float4*)(rS + kk); f1 = *(const float4*)(rS + kk + 4); }
        else if (region == 1) { f0 = *(const float4*)(rC + kk); f1 = *(const float4*)(rC + kk + 4); }
        else {
          float4 a0 = *(const float4*)(rS + kk), a1 = *(const float4*)(rS + kk + 4);
          float4 c0 = *(const float4*)(rC + kk), c1 = *(const float4*)(rC + kk + 4);
          f0 = make_float4(a0.x*c0.x, a0.y*c0.y, a0.z*c0.z, a0.w*c0.w);
          f1 = make_float4(a1.x*c1.x, a1.y*c1.y, a1.z*c1.z, a1.w*c1.w);
        }
      } else {
        float4 a0 = *(const float4*)(rS + kk), a1 = *(const float4*)(rS + kk + 4);
        float4 c0 = *(const float4*)(rC + kk), c1 = *(const float4*)(rC + kk + 4);
        f0 = make_float4(a0.x-c0.x, a0.y-c0.y, a0.z-c0.z, a0.w-c0.w);
        f1 = make_float4(a1.x-c1.x, a1.y-c1.y, a1.z-c1.z, a1.w-c1.w);
        if (region == 1) {
          f0 = make_float4(fabsf(f0.x), fabsf(f0.y), fabsf(f0.z), fabsf(f0.w));
          f1 = make_float4(fabsf(f1.x), fabsf(f1.y), fabsf(f1.z), fabsf(f1.w));
        }
      }
      *(uint4*)(Ab[buf] + row * 72 + colg + c8) = pack8(f0, f1);
    }
  };
  auto issueB = [&](const __half* W, int k0, int buf) {
    #pragma unroll
    for (int i = 0; i < 4; i++) {
      const int lin = tid + i * 512;
      const int br = lin >> 5, bc = (lin & 31) * 8;
      cp16(Bb[buf] + br * 264 + bc, W + (size_t)(k0 + br) * 256 + bc);
    }
    cp_commit();
  };

  // ---------------- GEMM 1 ----------------
  constexpr int NS1 = K1 / 64;
  stageA(0, 0);
  issueB(W1, 0, 0);
  for (int s = 0; s < NS1; s++) {
    const int cur = s & 1;
    cp_wait<0>();
    __syncthreads();
    if (s + 1 < NS1) { stageA(s + 1, cur ^ 1); issueB(W1, (s + 1) * 64, cur ^ 1); }
    #pragma unroll
    for (int ks = 0; ks < 64; ks += 16) {
      FragA af[2]; FragB bf[4];
      #pragma unroll
      for (int mi = 0; mi < 2; mi++)
        wmma::load_matrix_sync(af[mi], Ab[cur] + (wm * 32 + mi * 16) * 72 + ks, 72);
      #pragma unroll
      for (int ni = 0; ni < 4; ni++)
        wmma::load_matrix_sync(bf[ni], Bb[cur] + ks * 264 + wn * 64 + ni * 16, 264);
      #pragma unroll
      for (int mi = 0; mi < 2; mi++)
        #pragma unroll
        for (int ni = 0; ni < 4; ni++)
          wmma::mma_sync(acc[mi][ni], af[mi], bf[ni], acc[mi][ni]);
    }
  }

  // epilogue 1: relu -> fp16 -> h1
  #pragma unroll
  for (int mi = 0; mi < 2; mi++)
    #pragma unroll
    for (int ni = 0; ni < 4; ni++) {
      FragAccH hf;
      #pragma unroll
      for (int e = 0; e < hf.num_elements; e++)
        hf.x[e] = __float2half(fmaxf(acc[mi][ni].x[e], 0.f));
      wmma::store_matrix_sync(h1 + (wm * 32 + mi * 16) * 264 + wn * 64 + ni * 16,
                              hf, 264, wmma::mem_row_major);
    }
  __syncthreads();

  // refill bias tile with b2, prefetch first W2 slab
  if (tid < 264) {
    float v = (tid < 256) ? b2[tid] : 0.f;
    #pragma unroll
    for (int r = 0; r < 16; r++) bias32[r * 264 + tid] = v;
  }
  issueB(W2, 0, 0);
  __syncthreads();

  #pragma unroll
  for (int mi = 0; mi < 2; mi++)
    #pragma unroll
    for (int ni = 0; ni < 4; ni++)
      wmma::load_matrix_sync(acc[mi][ni], bias32 + wn * 64 + ni * 16, 264,
                             wmma::mem_row_major);

  // ---------------- GEMM 2 (A = h1 in smem, K=256) ----------------
  for (int s = 0; s < 4; s++) {
    const int cur = s & 1;
    cp_wait<0>();
    __syncthreads();
    if (s + 1 < 4) issueB(W2, (s + 1) * 64, cur ^ 1);
    #pragma unroll
    for (int ks = 0; ks < 64; ks += 16) {
      FragA af[2]; FragB bf[4];
      #pragma unroll
      for (int mi = 0; mi < 2; mi++)
        wmma::load_matrix_sync(af[mi], h1 + (wm * 32 + mi * 16) * 264 + s * 64 + ks, 264);
      #pragma unroll
      for (int ni = 0; ni < 4; ni++)
        wmma::load_matrix_sync(bf[ni], Bb[cur] + ks * 264 + wn * 64 + ni * 16, 264);
      #pragma unroll
      for (int mi = 0; mi < 2; mi++)
        #pragma unroll
        for (int ni = 0; ni < 4; ni++)
          wmma::mma_sync(acc[mi][ni], af[mi], bf[ni], acc[mi][ni]);
    }
  }

  // epilogue 2: (+bias already) -> fp16 -> global
  #pragma unroll
  for (int mi = 0; mi < 2; mi++)
    #pragma unroll
    for (int ni = 0; ni < 4; ni++) {
      FragAccH hf;
      #pragma unroll
      for (int e = 0; e < hf.num_elements; e++)
        hf.x[e] = __float2half(acc[mi][ni].x[e]);
      wmma::store_matrix_sync(outp + (size_t)(tBase + wm * 32 + mi * 16) * 256 +
                                  wn * 64 + ni * 16,
                              hf, 256, wmma::mem_row_major);
    }
}

// ===========================================================================
// Kernel C: fused (GEMM5 K=768, N=512, A=[cross|dif|prod]) -> relu -> smem h3
//           -> (GEMM6 K=512, N=256) -> +b -> LN -> weighted top-k sum -> out
// CTA: 512 threads, 64 tokens.
// ===========================================================================
__global__ __launch_bounds__(512, 1)
void fused56(const __half* __restrict__ cross, const __half* __restrict__ dif,
             const float* __restrict__ s_enc, const float* __restrict__ c_enc,
             const __half* __restrict__ W5, const float* __restrict__ b5,
             const __half* __restrict__ W6, const float* __restrict__ b6,
             const float* __restrict__ lng, const float* __restrict__ lnb,
             float* __restrict__ outp) {
  extern __shared__ char smem[];
  __half* h3 = (__half*)smem;                                   // 64x520
  __half* Bb[2] = { (__half*)(smem + 66560), (__half*)(smem + 99840) };   // 32x520 ea
  __half* Ab[2] = { (__half*)(smem + 133120), (__half*)(smem + 138240) }; // 64x40 ea
  float* bias32 = (float*)(smem + 143360);                      // 16x520
  float* sC = (float*)smem;                                     // 64x260 (aliases h3)

  const int tid = threadIdx.x, warp = tid >> 5, lane = tid & 31;
  const int tBase = blockIdx.x * 64;

  // staging assignment (first 256 threads)
  const int row = tid >> 2;            // 0..63 for tid<256
  const int c8 = (tid & 3) * 8;
  const int t_tok = tBase + (row & 63);
  const int bidx = t_tok >> 2, kidx = t_tok & 3;
  const float* rS = s_enc + ((size_t)bidx * NSTR + g_ti[kidx]) * D;
  const float* rC = c_enc + ((size_t)bidx * NSCA + g_tj[kidx]) * D;

  // bias tile b5 (512-wide)
  if (tid < 520) {
    float v = (tid < 512) ? b5[tid] : 0.f;
    #pragma unroll
    for (int r = 0; r < 16; r++) bias32[r * 520 + tid] = v;
  }
  __syncthreads();

  // ---------------- GEMM5: 64x512, K=768 ----------------
  const int wm5 = warp >> 3, wn5 = warp & 7;  // 2x8 warps; warp tile 32x64
  FragAcc acc5[2][4];
  #pragma unroll
  for (int mi = 0; mi < 2; mi++)
    #pragma unroll
    for (int ni = 0; ni < 4; ni++)
      wmma::load_matrix_sync(acc5[mi][ni], bias32 + wn5 * 64 + ni * 16, 520,
                             wmma::mem_row_major);

  auto stageA5 = [&](int s, int buf) {
    if (tid >= 256) return;
    const int k0 = s * 32;
    const int region = k0 >> 8;
    if (region < 2) {
      const __half* src = (region ? dif : cross) +
                          (size_t)t_tok * 256 + (k0 & 255) + c8;
      cp16(Ab[buf] + row * 40 + c8, src);
    } else {
      const int kk = (k0 & 255) + c8;
      float4 a0 = *(const float4*)(rS + kk), a1 = *(const float4*)(rS + kk + 4);
      float4 c0 = *(const float4*)(rC + kk), c1 = *(const float4*)(rC + kk + 4);
      float4 f0 = make_float4(a0.x*c0.x, a0.y*c0.y, a0.z*c0.z, a0.w*c0.w);
      float4 f1 = make_float4(a1.x*c1.x, a1.y*c1.y, a1.z*c1.z, a1.w*c1.w);
      *(uint4*)(Ab[buf] + row * 40 + c8) = pack8(f0, f1);
    }
  };
  auto issueB5 = [&](int k0, int buf) {
    #pragma unroll
    for (int i = 0; i < 4; i++) {
      const int lin = tid + i * 512;
      const int br = lin >> 6, bc = (lin & 63) * 8;
      cp16(Bb[buf] + br * 520 + bc, W5 + (size_t)(k0 + br) * 512 + bc);
    }
  };

  stageA5(0, 0);
  issueB5(0, 0);
  cp_commit();
  for (int s = 0; s < 24; s++) {
    const int cur = s & 1;
    cp_wait<0>();
    __syncthreads();
    if (s + 1 < 24) {
      stageA5(s + 1, cur ^ 1);
      issueB5((s + 1) * 32, cur ^ 1);
      cp_commit();
    }
    #pragma unroll
    for (int ks = 0; ks < 32; ks += 16) {
      FragA af[2]; FragB bf[4];
      #pragma unroll
      for (int mi = 0; mi < 2; mi++)
        wmma::load_matrix_sync(af[mi], Ab[cur] + (wm5 * 32 + mi * 16) * 40 + ks, 40);
      #pragma unroll
      for (int ni = 0; ni < 4; ni++)
        wmma::load_matrix_sync(bf[ni], Bb[cur] + ks * 520 + wn5 * 64 + ni * 16, 520);
      #pragma unroll
      for (int mi = 0; mi < 2; mi++)
        #pragma unroll
        for (int ni = 0; ni < 4; ni++)
          wmma::mma_sync(acc5[mi][ni], af[mi], bf[ni], acc5[mi][ni]);
    }
  }

  // epilogue 5: relu -> fp16 -> h3
  #pragma unroll
  for (int mi = 0; mi < 2; mi++)
    #pragma unroll
    for (int ni = 0; ni < 4; ni++) {
      FragAccH hf;
      #pragma unroll
      for (int e = 0; e < hf.num_elements; e++)
        hf.x[e] = __float2half(fmaxf(acc5[mi][ni].x[e], 0.f));
      wmma::store_matrix_sync(h3 + (wm5 * 32 + mi * 16) * 520 + wn5 * 64 + ni * 16,
                              hf, 520, wmma::mem_row_major);
    }

  // ---------------- GEMM6: 64x256, K=512 (A = h3) ----------------
  const int wm6 = warp >> 2, wn6 = warp & 3;  // 4x4 warps; warp tile 16x64
  FragAcc acc6[4];
  #pragma unroll
  for (int ni = 0; ni < 4; ni++) wmma::fill_fragment(acc6[ni], 0.f);

  auto issueB6 = [&](int k0, int buf) {
    #pragma unroll
    for (int i = 0; i < 2; i++) {
      const int lin = tid + i * 512;
      const int br = lin >> 5, bc = (lin & 31) * 8;
      cp16(Bb[buf] + br * 264 + bc, W6 + (size_t)(k0 + br) * 256 + bc);
    }
    cp_commit();
  };
  issueB6(0, 0);
  for (int s = 0; s < 16; s++) {
    const int cur = s & 1;
    cp_wait<0>();
    __syncthreads();
    if (s + 1 < 16) issueB6((s + 1) * 32, cur ^ 1);
    #pragma unroll
    for (int ks = 0; ks < 32; ks += 16) {
      FragA af; FragB bf[4];
      wmma::load_matrix_sync(af, h3 + (wm6 * 16) * 520 + s * 32 + ks, 520);
      #pragma unroll
      for (int ni = 0; ni < 4; ni++)
        wmma::load_matrix_sync(bf[ni], Bb[cur] + ks * 264 + wn6 * 64 + ni * 16, 264);
      #pragma unroll
      for (int ni = 0; ni < 4; ni++)
        wmma::mma_sync(acc6[ni], af, bf[ni], acc6[ni]);
    }
  }

  __syncthreads();  // all h3 reads done before overwrite with sC
  #pragma unroll
  for (int ni = 0; ni < 4; ni++)
    wmma::store_matrix_sync(sC + (wm6 * 16) * 260 + wn6 * 64 + ni * 16,
                            acc6[ni], 260, wmma::mem_row_major);
  __syncthreads();

  // LN + weighted top-k sum. Warp w owns rows 4w..4w+3 (= one batch).
  {
    const int w = warp;
    float b6c[8], gc[8], bc[8], x[4][8];
    #pragma unroll
    for (int j = 0; j < 8; j++) {
      const int c = lane + 32 * j;
      b6c[j] = b6[c]; gc[j] = lng[c]; bc[j] = lnb[c];
    }
    float o[8];
    #pragma unroll
    for (int j = 0; j < 8; j++) o[j] = 0.f;
    #pragma unroll
    for (int k = 0; k < 4; k++) {
      const int r = 4 * w + k;
      float s1 = 0.f, s2 = 0.f;
      #pragma unroll
      for (int j = 0; j < 8; j++) {
        float xv = sC[r * 260 + lane + 32 * j] + b6c[j];
        x[k][j] = xv; s1 += xv; s2 += xv * xv;
      }
      #pragma unroll
      for (int off = 16; off > 0; off >>= 1) {
        s1 += __shfl_xor_sync(0xffffffffu, s1, off);
        s2 += __shfl_xor_sync(0xffffffffu, s2, off);
      }
      const float mu  = s1 * (1.f / 256.f);
      const float var = s2 * (1.f / 256.f) - mu * mu;
      const float inv = rsqrtf(var + LN_EPS);
      const float wk  = g_w[k];
      #pragma unroll
      for (int j = 0; j < 8; j++) o[j] += wk * (x[k][j] - mu) * inv;
    }
    const int ob = (tBase >> 2) + w;
    #pragma unroll
    for (int j = 0; j < 8; j++) {
      const int c = lane + 32 * j;
      outp[(size_t)ob * 256 + c] = o[j] * gc[j] + bc[j];
    }
  }
}

// ---------------------------------------------------------------------------
extern "C" void kernel_launch(void* const* d_in, const int* in_sizes, int n_in,
                              void* d_out, int out_size) {
  const float* str   = (const float*)d_in[0];
  const float* sca   = (const float*)d_in[1];
  const float* pair  = (const float*)d_in[2];
  const float* temp  = (const float*)d_in[3];
  const float* cm_w1 = (const float*)d_in[4];
  const float* cm_b1 = (const float*)d_in[5];
  const float* cm_w2 = (const float*)d_in[6];
  const float* cm_b2 = (const float*)d_in[7];
  const float* df_w1 = (const float*)d_in[8];
  const float* df_b1 = (const float*)d_in[9];
  const float* df_w2 = (const float*)d_in[10];
  const float* df_b2 = (const float*)d_in[11];
  const float* fu_w1 = (const float*)d_in[12];
  const float* fu_b1 = (const float*)d_in[13];
  const float* fu_w2 = (const float*)d_in[14];
  const float* fu_b2 = (const float*)d_in[15];
  const float* lng   = (const float*)d_in[16];
  const float* lnb   = (const float*)d_in[17];
  float* out = (float*)d_out;

  __half *crossh, *difh, *hw1, *hw2, *hw3, *hw4, *hw5, *hw6;
  cudaGetSymbolAddress((void**)&crossh, g_crossh);
  cudaGetSymbolAddress((void**)&difh,   g_difh);
  cudaGetSymbolAddress((void**)&hw1,    g_hw1);
  cudaGetSymbolAddress((void**)&hw2,    g_hw2);
  cudaGetSymbolAddress((void**)&hw3,    g_hw3);
  cudaGetSymbolAddress((void**)&hw4,    g_hw4);
  cudaGetSymbolAddress((void**)&hw5,    g_hw5);
  cudaGetSymbolAddress((void**)&hw6,    g_hw6);

  prep_kernel<<<1, 32>>>(pair, temp);
  auto cvt = [&](const float* s, __half* d, int n) {
    to_half_kernel<<<(n / 4 + 255) / 256, 256>>>(s, d, n / 4);
  };
  cvt(cm_w1, hw1, 768 * 256);
  cvt(cm_w2, hw2, 256 * 256);
  cvt(df_w1, hw3, 512 * 256);
  cvt(df_w2, hw4, 256 * 256);
  cvt(fu_w1, hw5, 768 * 512);
  cvt(fu_w2, hw6, 512 * 256);

  const size_t SM_AB = 188928;
  const size_t SM_C  = 176640;

  { auto k = fused12<0, 768>;
    cudaFuncSetAttribute(k, cudaFuncAttributeMaxDynamicSharedMemorySize, (int)SM_AB);
    k<<<T_TOK / 128, 512, SM_AB>>>(str, sca, hw1, cm_b1, hw2, cm_b2, crossh); }
  { auto k = fused12<1, 512>;
    cudaFuncSetAttribute(k, cudaFuncAttributeMaxDynamicSharedMemorySize, (int)SM_AB);
    k<<<T_TOK / 128, 512, SM_AB>>>(str, sca, hw3, df_b1, hw4, df_b2, difh); }
  { auto k = fused56;
    cudaFuncSetAttribute(k, cudaFuncAttributeMaxDynamicSharedMemorySize, (int)SM_C);
    k<<<T_TOK / 64, 512, SM_C>>>(crossh, difh, str, sca, hw5, fu_b1, hw6, fu_b2,
                                 lng, lnb, out); }
}